// round 3
// baseline (speedup 1.0000x reference)
#include <cuda_runtime.h>
#include <cuda_fp16.h>

// GraphConv split into 2 kernels:
//  K1: pf = feats @ W_feat^T   -> stored fp16  ([131072,64])
//  K2: out = relu( inv_cnt * ( sum_{n valid} pf[idx_n] + srel . W_rel ) + b )
// Shapes fixed: B=8, P=K=16384, N=16, IN=64, REL=3, OUT=64.

#define LOG2_K 14
#define ROWS_TOTAL (8 * 16384)

__device__ __half g_pf[(size_t)ROWS_TOTAL * 64];   // 16 MB scratch

// ---------------------------------------------------------------------------
// Kernel 1: register-blocked SGEMM (fp32 math, fp16 store).
// Block = 256 thr, tile 128 rows x 64 outs. Thread (i,j): rows 8i..8i+7,
// output quad j. SMEM: feats 128x64 (32KB) + Wt 64x64 (16KB).
// ---------------------------------------------------------------------------
__global__ __launch_bounds__(256)
void proj_kernel(const float* __restrict__ feats,
                 const float* __restrict__ W,     // [64][67]
                 __half*      __restrict__ pf)
{
    __shared__ float a_s[128 * 64];
    __shared__ float w_s[64 * 64];    // w_s[k*64+o] = W[o*67+k]

    const int tid = threadIdx.x;

    for (int idx = tid; idx < 64 * 64; idx += 256) {
        int o = idx >> 6, k = idx & 63;
        w_s[k * 64 + o] = W[o * 67 + k];
    }
    {
        const float4* fg = reinterpret_cast<const float4*>(feats)
                           + (size_t)blockIdx.x * (128 * 16);
        float4* a4 = reinterpret_cast<float4*>(a_s);
        #pragma unroll
        for (int s = 0; s < 8; s++) a4[s * 256 + tid] = fg[s * 256 + tid];
    }
    __syncthreads();

    const int j = tid & 15;     // output quad
    const int i = tid >> 4;     // row group (0..15)

    const float4* a4 = reinterpret_cast<const float4*>(a_s);
    const float4* w4 = reinterpret_cast<const float4*>(w_s);

    float4 acc[8];
    #pragma unroll
    for (int r = 0; r < 8; r++) acc[r] = make_float4(0.f, 0.f, 0.f, 0.f);

    #pragma unroll
    for (int kq = 0; kq < 16; kq++) {
        const float4 b0 = w4[(4 * kq + 0) * 16 + j];
        const float4 b1 = w4[(4 * kq + 1) * 16 + j];
        const float4 b2 = w4[(4 * kq + 2) * 16 + j];
        const float4 b3 = w4[(4 * kq + 3) * 16 + j];
        #pragma unroll
        for (int r = 0; r < 8; r++) {
            const float4 a = a4[(i * 8 + r) * 16 + kq];
            acc[r].x = fmaf(a.x, b0.x, acc[r].x); acc[r].y = fmaf(a.x, b0.y, acc[r].y);
            acc[r].z = fmaf(a.x, b0.z, acc[r].z); acc[r].w = fmaf(a.x, b0.w, acc[r].w);
            acc[r].x = fmaf(a.y, b1.x, acc[r].x); acc[r].y = fmaf(a.y, b1.y, acc[r].y);
            acc[r].z = fmaf(a.y, b1.z, acc[r].z); acc[r].w = fmaf(a.y, b1.w, acc[r].w);
            acc[r].x = fmaf(a.z, b2.x, acc[r].x); acc[r].y = fmaf(a.z, b2.y, acc[r].y);
            acc[r].z = fmaf(a.z, b2.z, acc[r].z); acc[r].w = fmaf(a.z, b2.w, acc[r].w);
            acc[r].x = fmaf(a.w, b3.x, acc[r].x); acc[r].y = fmaf(a.w, b3.y, acc[r].y);
            acc[r].z = fmaf(a.w, b3.z, acc[r].z); acc[r].w = fmaf(a.w, b3.w, acc[r].w);
        }
    }

    // store fp16: each thread writes 8B per row (4 halves)
    uint2* pfo = reinterpret_cast<uint2*>(pf)
                 + (size_t)blockIdx.x * (128 * 16);
    #pragma unroll
    for (int r = 0; r < 8; r++) {
        __half2 lo = __float22half2_rn(make_float2(acc[r].x, acc[r].y));
        __half2 hi = __float22half2_rn(make_float2(acc[r].z, acc[r].w));
        uint2 v;
        v.x = *reinterpret_cast<unsigned*>(&lo);
        v.y = *reinterpret_cast<unsigned*>(&hi);
        pfo[(i * 8 + r) * 16 + j] = v;
    }
}

// ---------------------------------------------------------------------------
// Kernel 2: masked gather-sum of fp16 pf rows + rel term + epilogue.
// 8 lanes per row (lane owns 8 channels = one uint4 of fp16), 4 rows/warp.
// Invalid neighbors are skipped entirely (no load, no FMA).
// ---------------------------------------------------------------------------
#define THREADS 256
#define CHUNKS_PER_BLOCK 8
#define ROWS_PER_CHUNK 32   // 8 warps * 4 rows

__global__ __launch_bounds__(THREADS)
void gather_kernel(const __half* __restrict__ pf,
                   const int*    __restrict__ n_idxs,
                   const float*  __restrict__ nrel,
                   const int*    __restrict__ nvalid,
                   const float*  __restrict__ W,     // [64][67]
                   const float*  __restrict__ bias,
                   float*        __restrict__ out,
                   int rows_total)
{
    __shared__ float wr_s[3 * 64];   // wr_s[jc*64+o] = W[o*67 + 64 + jc]
    __shared__ float b_s[64];

    const int tid = threadIdx.x;
    for (int i = tid; i < 192; i += THREADS) {
        int jc = i >> 6, o = i & 63;
        wr_s[i] = W[o * 67 + 64 + jc];
    }
    if (tid < 64) b_s[tid] = bias[tid];
    __syncthreads();

    const int warp = tid >> 5;
    const int lane = tid & 31;
    const int q    = lane >> 3;   // row within warp (0..3)
    const int t    = lane & 7;    // channel octet id (channels 8t..8t+7)

    // per-lane constants: rel weights + bias for my 8 channels
    const float4 w0a = reinterpret_cast<const float4*>(wr_s)[0 * 16 + t * 2];
    const float4 w0b = reinterpret_cast<const float4*>(wr_s)[0 * 16 + t * 2 + 1];
    const float4 w1a = reinterpret_cast<const float4*>(wr_s)[1 * 16 + t * 2];
    const float4 w1b = reinterpret_cast<const float4*>(wr_s)[1 * 16 + t * 2 + 1];
    const float4 w2a = reinterpret_cast<const float4*>(wr_s)[2 * 16 + t * 2];
    const float4 w2b = reinterpret_cast<const float4*>(wr_s)[2 * 16 + t * 2 + 1];
    const float4 bga = reinterpret_cast<const float4*>(b_s)[t * 2];
    const float4 bgb = reinterpret_cast<const float4*>(b_s)[t * 2 + 1];

    for (int chunk = 0; chunk < CHUNKS_PER_BLOCK; chunk++) {
        const int rowbase = (blockIdx.x * CHUNKS_PER_BLOCK + chunk) * ROWS_PER_CHUNK
                            + warp * 4;
        if (rowbase >= rows_total) return;
        const int row = rowbase + q;
        const int b   = row >> LOG2_K;

        // each lane owns 2 neighbors of its row: n=t and n=t+8
        const int   idxA = n_idxs[row * 16 + t];
        const int   idxB = n_idxs[row * 16 + 8 + t];
        const float vA   = (float)nvalid[row * 16 + t];
        const float vB   = (float)nvalid[row * 16 + 8 + t];

        const float* rp = nrel + (size_t)row * 48;
        float r0 = rp[t * 3 + 0] * vA + rp[(t + 8) * 3 + 0] * vB;
        float r1 = rp[t * 3 + 1] * vA + rp[(t + 8) * 3 + 1] * vB;
        float r2 = rp[t * 3 + 2] * vA + rp[(t + 8) * 3 + 2] * vB;
        float cnt = vA + vB;

        #pragma unroll
        for (int m = 1; m < 8; m <<= 1) {
            r0  += __shfl_xor_sync(0xffffffffu, r0,  m);
            r1  += __shfl_xor_sync(0xffffffffu, r1,  m);
            r2  += __shfl_xor_sync(0xffffffffu, r2,  m);
            cnt += __shfl_xor_sync(0xffffffffu, cnt, m);
        }
        const float inv = (cnt > 0.0f) ? (1.0f / cnt) : 0.0f;

        // gather-sum of fp16 pf rows; invalid neighbors skipped (no load)
        const uint4* pb = reinterpret_cast<const uint4*>(pf)
                          + ((size_t)b << LOG2_K) * 8;
        float a0 = 0.f, a1 = 0.f, a2 = 0.f, a3 = 0.f;
        float a4 = 0.f, a5 = 0.f, a6 = 0.f, a7 = 0.f;

        #pragma unroll
        for (int n = 0; n < 16; n++) {
            const int   src  = (lane & 24) | (n & 7);
            const int   idxn = __shfl_sync(0xffffffffu, (n < 8) ? idxA : idxB, src);
            const float vn   = __shfl_sync(0xffffffffu, (n < 8) ? vA   : vB,   src);
            if (vn > 0.0f) {
                const uint4 h = pb[(size_t)idxn * 8 + t];
                const float2 f0 = __half22float2(*reinterpret_cast<const __half2*>(&h.x));
                const float2 f1 = __half22float2(*reinterpret_cast<const __half2*>(&h.y));
                const float2 f2 = __half22float2(*reinterpret_cast<const __half2*>(&h.z));
                const float2 f3 = __half22float2(*reinterpret_cast<const __half2*>(&h.w));
                a0 += f0.x; a1 += f0.y; a2 += f1.x; a3 += f1.y;
                a4 += f2.x; a5 += f2.y; a6 += f3.x; a7 += f3.y;
            }
        }

        // rel-channel contribution (already valid-masked)
        a0 = fmaf(r0, w0a.x, a0); a1 = fmaf(r0, w0a.y, a1);
        a2 = fmaf(r0, w0a.z, a2); a3 = fmaf(r0, w0a.w, a3);
        a4 = fmaf(r0, w0b.x, a4); a5 = fmaf(r0, w0b.y, a5);
        a6 = fmaf(r0, w0b.z, a6); a7 = fmaf(r0, w0b.w, a7);
        a0 = fmaf(r1, w1a.x, a0); a1 = fmaf(r1, w1a.y, a1);
        a2 = fmaf(r1, w1a.z, a2); a3 = fmaf(r1, w1a.w, a3);
        a4 = fmaf(r1, w1b.x, a4); a5 = fmaf(r1, w1b.y, a5);
        a6 = fmaf(r1, w1b.z, a6); a7 = fmaf(r1, w1b.w, a7);
        a0 = fmaf(r2, w2a.x, a0); a1 = fmaf(r2, w2a.y, a1);
        a2 = fmaf(r2, w2a.z, a2); a3 = fmaf(r2, w2a.w, a3);
        a4 = fmaf(r2, w2b.x, a4); a5 = fmaf(r2, w2b.y, a5);
        a6 = fmaf(r2, w2b.z, a6); a7 = fmaf(r2, w2b.w, a7);

        float4 resA, resB;
        resA.x = fmaxf(fmaf(a0, inv, bga.x), 0.0f);
        resA.y = fmaxf(fmaf(a1, inv, bga.y), 0.0f);
        resA.z = fmaxf(fmaf(a2, inv, bga.z), 0.0f);
        resA.w = fmaxf(fmaf(a3, inv, bga.w), 0.0f);
        resB.x = fmaxf(fmaf(a4, inv, bgb.x), 0.0f);
        resB.y = fmaxf(fmaf(a5, inv, bgb.y), 0.0f);
        resB.z = fmaxf(fmaf(a6, inv, bgb.z), 0.0f);
        resB.w = fmaxf(fmaf(a7, inv, bgb.w), 0.0f);

        float4* op = reinterpret_cast<float4*>(out) + (size_t)row * 16;
        op[t * 2]     = resA;
        op[t * 2 + 1] = resB;
    }
}

extern "C" void kernel_launch(void* const* d_in, const int* in_sizes, int n_in,
                              void* d_out, int out_size)
{
    // metadata order: keys, points, feats, n_idxs, neighbor_rel,
    //                 neighbor_valid, W, b
    const float* feats  = (const float*)d_in[2];
    const int*   n_idxs = (const int*)  d_in[3];
    const float* nrel   = (const float*)d_in[4];
    const int*   nvalid = (const int*)  d_in[5];
    const float* W      = (const float*)d_in[6];
    const float* bias   = (const float*)d_in[7];
    float*       out    = (float*)d_out;

    const int rows_total = out_size / 64;   // 131072

    __half* pf = nullptr;
    cudaGetSymbolAddress((void**)&pf, g_pf);

    proj_kernel<<<rows_total / 128, 256>>>(feats, W, pf);

    const int rows_per_block = CHUNKS_PER_BLOCK * ROWS_PER_CHUNK;  // 256
    const int grid = (rows_total + rows_per_block - 1) / rows_per_block;
    gather_kernel<<<grid, THREADS>>>(pf, n_idxs, nrel, nvalid,
                                     W, bias, out, rows_total);
}

// round 4
// speedup vs baseline: 1.2783x; 1.2783x over previous
#include <cuda_runtime.h>
#include <cuda_fp16.h>

// GraphConv split into 2 kernels:
//  K1: pf = feats @ W_feat^T   -> stored fp16  ([131072,64])
//  K2: out = relu( inv_cnt * ( sum_{n valid} pf[idx_n] + srel . W_rel ) + b )
// Shapes fixed: B=8, P=K=16384, N=16, IN=64, REL=3, OUT=64.

#define LOG2_K 14
#define ROWS_TOTAL (8 * 16384)

__device__ __half g_pf[(size_t)ROWS_TOTAL * 64];   // 16 MB scratch

// ---------------------------------------------------------------------------
// Kernel 1: register-blocked SGEMM (fp32 math, fp16 store).
// Block = 256 thr, tile 128 rows x 64 outs.
// ---------------------------------------------------------------------------
__global__ __launch_bounds__(256)
void proj_kernel(const float* __restrict__ feats,
                 const float* __restrict__ W,     // [64][67]
                 __half*      __restrict__ pf)
{
    __shared__ float a_s[128 * 64];
    __shared__ float w_s[64 * 64];    // w_s[k*64+o] = W[o*67+k]

    const int tid = threadIdx.x;

    for (int idx = tid; idx < 64 * 64; idx += 256) {
        int o = idx >> 6, k = idx & 63;
        w_s[k * 64 + o] = W[o * 67 + k];
    }
    {
        const float4* fg = reinterpret_cast<const float4*>(feats)
                           + (size_t)blockIdx.x * (128 * 16);
        float4* a4 = reinterpret_cast<float4*>(a_s);
        #pragma unroll
        for (int s = 0; s < 8; s++) a4[s * 256 + tid] = fg[s * 256 + tid];
    }
    __syncthreads();

    const int j = tid & 15;     // output quad
    const int i = tid >> 4;     // row group (0..15)

    const float4* a4 = reinterpret_cast<const float4*>(a_s);
    const float4* w4 = reinterpret_cast<const float4*>(w_s);

    float4 acc[8];
    #pragma unroll
    for (int r = 0; r < 8; r++) acc[r] = make_float4(0.f, 0.f, 0.f, 0.f);

    #pragma unroll
    for (int kq = 0; kq < 16; kq++) {
        const float4 b0 = w4[(4 * kq + 0) * 16 + j];
        const float4 b1 = w4[(4 * kq + 1) * 16 + j];
        const float4 b2 = w4[(4 * kq + 2) * 16 + j];
        const float4 b3 = w4[(4 * kq + 3) * 16 + j];
        #pragma unroll
        for (int r = 0; r < 8; r++) {
            const float4 a = a4[(i * 8 + r) * 16 + kq];
            acc[r].x = fmaf(a.x, b0.x, acc[r].x); acc[r].y = fmaf(a.x, b0.y, acc[r].y);
            acc[r].z = fmaf(a.x, b0.z, acc[r].z); acc[r].w = fmaf(a.x, b0.w, acc[r].w);
            acc[r].x = fmaf(a.y, b1.x, acc[r].x); acc[r].y = fmaf(a.y, b1.y, acc[r].y);
            acc[r].z = fmaf(a.y, b1.z, acc[r].z); acc[r].w = fmaf(a.y, b1.w, acc[r].w);
            acc[r].x = fmaf(a.z, b2.x, acc[r].x); acc[r].y = fmaf(a.z, b2.y, acc[r].y);
            acc[r].z = fmaf(a.z, b2.z, acc[r].z); acc[r].w = fmaf(a.z, b2.w, acc[r].w);
            acc[r].x = fmaf(a.w, b3.x, acc[r].x); acc[r].y = fmaf(a.w, b3.y, acc[r].y);
            acc[r].z = fmaf(a.w, b3.z, acc[r].z); acc[r].w = fmaf(a.w, b3.w, acc[r].w);
        }
    }

    uint2* pfo = reinterpret_cast<uint2*>(pf)
                 + (size_t)blockIdx.x * (128 * 16);
    #pragma unroll
    for (int r = 0; r < 8; r++) {
        __half2 lo = __float22half2_rn(make_float2(acc[r].x, acc[r].y));
        __half2 hi = __float22half2_rn(make_float2(acc[r].z, acc[r].w));
        uint2 v;
        v.x = *reinterpret_cast<unsigned*>(&lo);
        v.y = *reinterpret_cast<unsigned*>(&hi);
        pfo[(i * 8 + r) * 16 + j] = v;
    }
}

// ---------------------------------------------------------------------------
// Kernel 2: gather-sum of fp16 pf rows. 16 lanes/row (lane owns 4 channels =
// uint2), 2 rows/warp. ALL 16 loads unconditional (full MLP); invalid
// neighbors are redirected to batch-row 0 (hot L1 line) and killed by *vn.
// ---------------------------------------------------------------------------
#define THREADS 256
#define CHUNKS_PER_BLOCK 8
#define ROWS_PER_CHUNK 16   // 8 warps * 2 rows

__global__ __launch_bounds__(THREADS)
void gather_kernel(const __half* __restrict__ pf,
                   const int*    __restrict__ n_idxs,
                   const float*  __restrict__ nrel,
                   const int*    __restrict__ nvalid,
                   const float*  __restrict__ W,     // [64][67]
                   const float*  __restrict__ bias,
                   float*        __restrict__ out,
                   int rows_total)
{
    __shared__ float wr_s[3 * 64];   // wr_s[jc*64+o] = W[o*67 + 64 + jc]
    __shared__ float b_s[64];

    const int tid = threadIdx.x;
    for (int i = tid; i < 192; i += THREADS) {
        int jc = i >> 6, o = i & 63;
        wr_s[i] = W[o * 67 + 64 + jc];
    }
    if (tid < 64) b_s[tid] = bias[tid];
    __syncthreads();

    const int warp = tid >> 5;
    const int lane = tid & 31;
    const int t    = lane & 15;   // channel quad id (channels 4t..4t+3)

    const float4* wr4 = reinterpret_cast<const float4*>(wr_s);
    const float4  b4  = reinterpret_cast<const float4*>(b_s)[t];
    const float4  w0  = wr4[0 * 16 + t];
    const float4  w1  = wr4[1 * 16 + t];
    const float4  w2  = wr4[2 * 16 + t];

    for (int chunk = 0; chunk < CHUNKS_PER_BLOCK; chunk++) {
        const int rowA = (blockIdx.x * CHUNKS_PER_BLOCK + chunk) * ROWS_PER_CHUNK
                         + warp * 2;
        if (rowA >= rows_total) return;
        const int row = rowA + (lane >> 4);
        const int b   = row >> LOG2_K;

        // lane covers neighbor (lane&15) of its half-warp's row
        const int   myidx = n_idxs[rowA * 16 + lane];
        const float myval = (float)nvalid[rowA * 16 + lane];
        const float* relp = nrel + rowA * 48 + lane * 3;
        float r0 = relp[0] * myval;
        float r1 = relp[1] * myval;
        float r2 = relp[2] * myval;
        float cnt = myval;

        #pragma unroll
        for (int m = 1; m < 16; m <<= 1) {
            r0  += __shfl_xor_sync(0xffffffffu, r0,  m);
            r1  += __shfl_xor_sync(0xffffffffu, r1,  m);
            r2  += __shfl_xor_sync(0xffffffffu, r2,  m);
            cnt += __shfl_xor_sync(0xffffffffu, cnt, m);
        }
        const float inv = (cnt > 0.0f) ? (1.0f / cnt) : 0.0f;

        // redirect invalid neighbors to row 0 of the batch (stays in L1)
        const int ieff = (myval > 0.0f) ? myidx : 0;

        const uint2* pb = reinterpret_cast<const uint2*>(pf)
                          + ((size_t)b << LOG2_K) * 16;
        float a0 = 0.f, a1 = 0.f, a2 = 0.f, a3 = 0.f;

        #pragma unroll
        for (int n = 0; n < 16; n++) {
            const int   src  = (lane & 16) + n;
            const int   idxn = __shfl_sync(0xffffffffu, ieff,  src);
            const float vn   = __shfl_sync(0xffffffffu, myval, src);
            const uint2 h = pb[(size_t)idxn * 16 + t];
            const float2 f0 = __half22float2(*reinterpret_cast<const __half2*>(&h.x));
            const float2 f1 = __half22float2(*reinterpret_cast<const __half2*>(&h.y));
            a0 = fmaf(f0.x, vn, a0);
            a1 = fmaf(f0.y, vn, a1);
            a2 = fmaf(f1.x, vn, a2);
            a3 = fmaf(f1.y, vn, a3);
        }

        // rel-channel contribution (already valid-masked)
        a0 = fmaf(r0, w0.x, a0); a1 = fmaf(r0, w0.y, a1);
        a2 = fmaf(r0, w0.z, a2); a3 = fmaf(r0, w0.w, a3);
        a0 = fmaf(r1, w1.x, a0); a1 = fmaf(r1, w1.y, a1);
        a2 = fmaf(r1, w1.z, a2); a3 = fmaf(r1, w1.w, a3);
        a0 = fmaf(r2, w2.x, a0); a1 = fmaf(r2, w2.y, a1);
        a2 = fmaf(r2, w2.z, a2); a3 = fmaf(r2, w2.w, a3);

        float4 res;
        res.x = fmaxf(fmaf(a0, inv, b4.x), 0.0f);
        res.y = fmaxf(fmaf(a1, inv, b4.y), 0.0f);
        res.z = fmaxf(fmaf(a2, inv, b4.z), 0.0f);
        res.w = fmaxf(fmaf(a3, inv, b4.w), 0.0f);
        reinterpret_cast<float4*>(out)[(size_t)row * 16 + t] = res;
    }
}

extern "C" void kernel_launch(void* const* d_in, const int* in_sizes, int n_in,
                              void* d_out, int out_size)
{
    // metadata order: keys, points, feats, n_idxs, neighbor_rel,
    //                 neighbor_valid, W, b
    const float* feats  = (const float*)d_in[2];
    const int*   n_idxs = (const int*)  d_in[3];
    const float* nrel   = (const float*)d_in[4];
    const int*   nvalid = (const int*)  d_in[5];
    const float* W      = (const float*)d_in[6];
    const float* bias   = (const float*)d_in[7];
    float*       out    = (float*)d_out;

    const int rows_total = out_size / 64;   // 131072

    __half* pf = nullptr;
    cudaGetSymbolAddress((void**)&pf, g_pf);

    proj_kernel<<<rows_total / 128, 256>>>(feats, W, pf);

    const int rows_per_block = CHUNKS_PER_BLOCK * ROWS_PER_CHUNK;  // 128
    const int grid = (rows_total + rows_per_block - 1) / rows_per_block;
    gather_kernel<<<grid, THREADS>>>(pf, n_idxs, nrel, nvalid,
                                     W, bias, out, rows_total);
}

// round 5
// speedup vs baseline: 1.5198x; 1.1889x over previous
#include <cuda_runtime.h>
#include <cuda_fp16.h>

// GraphConv split into 2 kernels:
//  K1: pf = feats @ W_feat^T -> fp16 ([131072+1, 64]; last row = zeros sentinel)
//  K2: out = relu( inv_cnt * ( sum_{n valid} pf[idx_n] + srel . W_rel ) + b )
// Shapes fixed: B=8, P=K=16384, N=16, IN=64, REL=3, OUT=64.

#define LOG2_K 14
#define ROWS_TOTAL (8 * 16384)
#define ZROW ROWS_TOTAL   // zero sentinel row index in pf

__device__ __half g_pf[((size_t)ROWS_TOTAL + 1) * 64];   // 16 MB + 128 B

// ---------------------------------------------------------------------------
// Kernel 1: register-blocked SGEMM (fp32 math, fp16 store).
// Block = 256 thr, tile 128 rows x 64 outs. Block 0 also zeroes the sentinel.
// ---------------------------------------------------------------------------
__global__ __launch_bounds__(256)
void proj_kernel(const float* __restrict__ feats,
                 const float* __restrict__ W,     // [64][67]
                 __half*      __restrict__ pf)
{
    __shared__ float a_s[128 * 64];
    __shared__ float w_s[64 * 64];    // w_s[k*64+o] = W[o*67+k]

    const int tid = threadIdx.x;

    if (blockIdx.x == 0 && tid < 16) {
        uint2 z; z.x = 0u; z.y = 0u;
        reinterpret_cast<uint2*>(pf)[(size_t)ZROW * 16 + tid] = z;
    }

    for (int idx = tid; idx < 64 * 64; idx += 256) {
        int o = idx >> 6, k = idx & 63;
        w_s[k * 64 + o] = W[o * 67 + k];
    }
    {
        const float4* fg = reinterpret_cast<const float4*>(feats)
                           + (size_t)blockIdx.x * (128 * 16);
        float4* a4 = reinterpret_cast<float4*>(a_s);
        #pragma unroll
        for (int s = 0; s < 8; s++) a4[s * 256 + tid] = fg[s * 256 + tid];
    }
    __syncthreads();

    const int j = tid & 15;     // output quad
    const int i = tid >> 4;     // row group (0..15)

    const float4* a4 = reinterpret_cast<const float4*>(a_s);
    const float4* w4 = reinterpret_cast<const float4*>(w_s);

    float4 acc[8];
    #pragma unroll
    for (int r = 0; r < 8; r++) acc[r] = make_float4(0.f, 0.f, 0.f, 0.f);

    #pragma unroll
    for (int kq = 0; kq < 16; kq++) {
        const float4 b0 = w4[(4 * kq + 0) * 16 + j];
        const float4 b1 = w4[(4 * kq + 1) * 16 + j];
        const float4 b2 = w4[(4 * kq + 2) * 16 + j];
        const float4 b3 = w4[(4 * kq + 3) * 16 + j];
        #pragma unroll
        for (int r = 0; r < 8; r++) {
            const float4 a = a4[(i * 8 + r) * 16 + kq];
            acc[r].x = fmaf(a.x, b0.x, acc[r].x); acc[r].y = fmaf(a.x, b0.y, acc[r].y);
            acc[r].z = fmaf(a.x, b0.z, acc[r].z); acc[r].w = fmaf(a.x, b0.w, acc[r].w);
            acc[r].x = fmaf(a.y, b1.x, acc[r].x); acc[r].y = fmaf(a.y, b1.y, acc[r].y);
            acc[r].z = fmaf(a.y, b1.z, acc[r].z); acc[r].w = fmaf(a.y, b1.w, acc[r].w);
            acc[r].x = fmaf(a.z, b2.x, acc[r].x); acc[r].y = fmaf(a.z, b2.y, acc[r].y);
            acc[r].z = fmaf(a.z, b2.z, acc[r].z); acc[r].w = fmaf(a.z, b2.w, acc[r].w);
            acc[r].x = fmaf(a.w, b3.x, acc[r].x); acc[r].y = fmaf(a.w, b3.y, acc[r].y);
            acc[r].z = fmaf(a.w, b3.z, acc[r].z); acc[r].w = fmaf(a.w, b3.w, acc[r].w);
        }
    }

    uint2* pfo = reinterpret_cast<uint2*>(pf)
                 + (size_t)blockIdx.x * (128 * 16);
    #pragma unroll
    for (int r = 0; r < 8; r++) {
        __half2 lo = __float22half2_rn(make_float2(acc[r].x, acc[r].y));
        __half2 hi = __float22half2_rn(make_float2(acc[r].z, acc[r].w));
        uint2 v;
        v.x = *reinterpret_cast<unsigned*>(&lo);
        v.y = *reinterpret_cast<unsigned*>(&hi);
        pfo[(i * 8 + r) * 16 + j] = v;
    }
}

// ---------------------------------------------------------------------------
// Kernel 2: gather-sum of fp16 pf rows. 16 lanes/row (lane owns 4 channels),
// 2 rows/warp. Indices/valids fetched as int4 L1-broadcasts, gather addresses
// are pure register math -> 16 unconditional LDG.64 back-to-back (MLP=16).
// Invalid neighbors load the zero sentinel row (no masking in the hot loop).
// ---------------------------------------------------------------------------
#define THREADS 256
#define CHUNKS_PER_BLOCK 2
#define ROWS_PER_CHUNK 16   // 8 warps * 2 rows

#define EIDX(V, I) ((V) ? (base + (I)) : ZROW)

__global__ __launch_bounds__(THREADS)
void gather_kernel(const __half* __restrict__ pf,
                   const int*    __restrict__ n_idxs,
                   const float*  __restrict__ nrel,
                   const int*    __restrict__ nvalid,
                   const float*  __restrict__ W,     // [64][67]
                   const float*  __restrict__ bias,
                   float*        __restrict__ out,
                   int rows_total)
{
    __shared__ float wr_s[3 * 64];   // wr_s[jc*64+o] = W[o*67 + 64 + jc]
    __shared__ float b_s[64];

    const int tid = threadIdx.x;
    for (int i = tid; i < 192; i += THREADS) {
        int jc = i >> 6, o = i & 63;
        wr_s[i] = W[o * 67 + 64 + jc];
    }
    if (tid < 64) b_s[tid] = bias[tid];
    __syncthreads();

    const int warp = tid >> 5;
    const int lane = tid & 31;
    const int g    = lane >> 4;
    const int t    = lane & 15;   // channel quad id

    const float4* wr4 = reinterpret_cast<const float4*>(wr_s);
    const float4  b4  = reinterpret_cast<const float4*>(b_s)[t];
    const float4  w0  = wr4[0 * 16 + t];
    const float4  w1  = wr4[1 * 16 + t];
    const float4  w2  = wr4[2 * 16 + t];

    const uint2* pg = reinterpret_cast<const uint2*>(pf);

    for (int chunk = 0; chunk < CHUNKS_PER_BLOCK; chunk++) {
        const int rowA = (blockIdx.x * CHUNKS_PER_BLOCK + chunk) * ROWS_PER_CHUNK
                         + warp * 2;
        if (rowA >= rows_total) return;
        const int row  = rowA + g;
        const int base = (row >> LOG2_K) << LOG2_K;   // batch base row in pf

        // group-broadcast loads of this row's 16 indices + 16 valids
        const int4* ip = reinterpret_cast<const int4*>(n_idxs + row * 16);
        const int4* vp = reinterpret_cast<const int4*>(nvalid + row * 16);
        const int4 ia = ip[0], ib = ip[1], ic = ip[2], id = ip[3];
        const int4 va = vp[0], vb = vp[1], vc = vp[2], vd = vp[3];

        // effective pf row per neighbor (invalid -> zero sentinel)
        const int e0  = EIDX(va.x, ia.x), e1  = EIDX(va.y, ia.y);
        const int e2  = EIDX(va.z, ia.z), e3  = EIDX(va.w, ia.w);
        const int e4  = EIDX(vb.x, ib.x), e5  = EIDX(vb.y, ib.y);
        const int e6  = EIDX(vb.z, ib.z), e7  = EIDX(vb.w, ib.w);
        const int e8  = EIDX(vc.x, ic.x), e9  = EIDX(vc.y, ic.y);
        const int e10 = EIDX(vc.z, ic.z), e11 = EIDX(vc.w, ic.w);
        const int e12 = EIDX(vd.x, id.x), e13 = EIDX(vd.y, id.y);
        const int e14 = EIDX(vd.z, id.z), e15 = EIDX(vd.w, id.w);

        const int icnt = va.x + va.y + va.z + va.w + vb.x + vb.y + vb.z + vb.w
                       + vc.x + vc.y + vc.z + vc.w + vd.x + vd.y + vd.z + vd.w;
        const float inv = (icnt > 0) ? (1.0f / (float)icnt) : 0.0f;

        // rel term: lane covers neighbor (lane&15) of row rowA+(lane>>4);
        // masked per-lane, reduced within the 16-lane group (off load path)
        const int vm = (g == 0)
            ? ((t < 8) ? ((t < 4) ? (&va.x)[t] : (&vb.x)[t - 4])
                       : ((t < 12) ? (&vc.x)[t - 8] : (&vd.x)[t - 12]))
            : 0;  // placeholder; replaced below by per-lane load for simplicity
        (void)vm;
        const float myval = (float)nvalid[rowA * 16 + lane];
        const float* relp = nrel + rowA * 48 + lane * 3;
        float r0 = relp[0] * myval;
        float r1 = relp[1] * myval;
        float r2 = relp[2] * myval;
        #pragma unroll
        for (int m = 1; m < 16; m <<= 1) {
            r0 += __shfl_xor_sync(0xffffffffu, r0, m);
            r1 += __shfl_xor_sync(0xffffffffu, r1, m);
            r2 += __shfl_xor_sync(0xffffffffu, r2, m);
        }

        // 16 unconditional gathers (addresses ready -> full MLP)
        const uint2 h0  = pg[(size_t)e0  * 16 + t];
        const uint2 h1  = pg[(size_t)e1  * 16 + t];
        const uint2 h2  = pg[(size_t)e2  * 16 + t];
        const uint2 h3  = pg[(size_t)e3  * 16 + t];
        const uint2 h4  = pg[(size_t)e4  * 16 + t];
        const uint2 h5  = pg[(size_t)e5  * 16 + t];
        const uint2 h6  = pg[(size_t)e6  * 16 + t];
        const uint2 h7  = pg[(size_t)e7  * 16 + t];
        const uint2 h8  = pg[(size_t)e8  * 16 + t];
        const uint2 h9  = pg[(size_t)e9  * 16 + t];
        const uint2 h10 = pg[(size_t)e10 * 16 + t];
        const uint2 h11 = pg[(size_t)e11 * 16 + t];
        const uint2 h12 = pg[(size_t)e12 * 16 + t];
        const uint2 h13 = pg[(size_t)e13 * 16 + t];
        const uint2 h14 = pg[(size_t)e14 * 16 + t];
        const uint2 h15 = pg[(size_t)e15 * 16 + t];

        float a0 = 0.f, a1 = 0.f, a2 = 0.f, a3 = 0.f;
        #define ACCUM(H) do {                                                  \
            const float2 f0 = __half22float2(*reinterpret_cast<const __half2*>(&(H).x)); \
            const float2 f1 = __half22float2(*reinterpret_cast<const __half2*>(&(H).y)); \
            a0 += f0.x; a1 += f0.y; a2 += f1.x; a3 += f1.y;                    \
        } while (0)
        ACCUM(h0);  ACCUM(h1);  ACCUM(h2);  ACCUM(h3);
        ACCUM(h4);  ACCUM(h5);  ACCUM(h6);  ACCUM(h7);
        ACCUM(h8);  ACCUM(h9);  ACCUM(h10); ACCUM(h11);
        ACCUM(h12); ACCUM(h13); ACCUM(h14); ACCUM(h15);
        #undef ACCUM

        a0 = fmaf(r0, w0.x, a0); a1 = fmaf(r0, w0.y, a1);
        a2 = fmaf(r0, w0.z, a2); a3 = fmaf(r0, w0.w, a3);
        a0 = fmaf(r1, w1.x, a0); a1 = fmaf(r1, w1.y, a1);
        a2 = fmaf(r1, w1.z, a2); a3 = fmaf(r1, w1.w, a3);
        a0 = fmaf(r2, w2.x, a0); a1 = fmaf(r2, w2.y, a1);
        a2 = fmaf(r2, w2.z, a2); a3 = fmaf(r2, w2.w, a3);

        float4 res;
        res.x = fmaxf(fmaf(a0, inv, b4.x), 0.0f);
        res.y = fmaxf(fmaf(a1, inv, b4.y), 0.0f);
        res.z = fmaxf(fmaf(a2, inv, b4.z), 0.0f);
        res.w = fmaxf(fmaf(a3, inv, b4.w), 0.0f);
        reinterpret_cast<float4*>(out)[(size_t)row * 16 + t] = res;
    }
}

extern "C" void kernel_launch(void* const* d_in, const int* in_sizes, int n_in,
                              void* d_out, int out_size)
{
    // metadata order: keys, points, feats, n_idxs, neighbor_rel,
    //                 neighbor_valid, W, b
    const float* feats  = (const float*)d_in[2];
    const int*   n_idxs = (const int*)  d_in[3];
    const float* nrel   = (const float*)d_in[4];
    const int*   nvalid = (const int*)  d_in[5];
    const float* W      = (const float*)d_in[6];
    const float* bias   = (const float*)d_in[7];
    float*       out    = (float*)d_out;

    const int rows_total = out_size / 64;   // 131072

    __half* pf = nullptr;
    cudaGetSymbolAddress((void**)&pf, g_pf);

    proj_kernel<<<rows_total / 128, 256>>>(feats, W, pf);

    const int rows_per_block = CHUNKS_PER_BLOCK * ROWS_PER_CHUNK;  // 32
    const int grid = (rows_total + rows_per_block - 1) / rows_per_block;  // 4096
    gather_kernel<<<grid, THREADS>>>(pf, n_idxs, nrel, nvalid,
                                     W, bias, out, rows_total);
}

// round 6
// speedup vs baseline: 1.8231x; 1.1996x over previous
#include <cuda_runtime.h>
#include <cuda_fp16.h>
#include <cstdint>

// GraphConv, 3-kernel pipeline:
//  K0 meta:  eidx[row][16] = valid ? batch_base+idx : ZROW ; meta[row]=(r0,r1,r2,inv)
//  K1 proj:  pf = fp16( feats @ W_feat^T )  via mma.sync (HMMA), fp32 accum
//  K2 gather: out = relu( inv*( sum pf[eidx_n] + srel.W_rel ) + b )
// Shapes fixed: B=8, P=K=16384, N=16, IN=64, REL=3, OUT=64.

#define LOG2_K 14
#define ROWS_TOTAL (8 * 16384)
#define ZROW ROWS_TOTAL

__device__ __align__(16) __half g_pf[((size_t)ROWS_TOTAL + 1) * 64];
__device__ __align__(16) int    g_eidx[(size_t)ROWS_TOTAL * 16];
__device__ __align__(16) float4 g_meta[ROWS_TOTAL];

__device__ __forceinline__ uint32_t smem_u32(const void* p) {
    uint32_t a;
    asm("{ .reg .u64 t; cvta.to.shared.u64 t, %1; cvt.u32.u64 %0, t; }"
        : "=r"(a) : "l"(p));
    return a;
}

// ---------------------------------------------------------------------------
// Kernel 0: per-row metadata. Warp handles 2 rows (16 lanes each).
// ---------------------------------------------------------------------------
__global__ __launch_bounds__(256)
void meta_kernel(const int*   __restrict__ n_idxs,
                 const int*   __restrict__ nvalid,
                 const float* __restrict__ nrel,
                 int*         __restrict__ eidx,
                 float4*      __restrict__ meta,
                 __half*      __restrict__ pf,
                 int rows_total)
{
    const int tid  = threadIdx.x;
    if (blockIdx.x == 0 && tid < 16) {   // zero the sentinel pf row
        uint2 z; z.x = 0u; z.y = 0u;
        reinterpret_cast<uint2*>(pf)[(size_t)ZROW * 16 + tid] = z;
    }

    const int warp = tid >> 5;
    const int lane = tid & 31;
    const int rowA = blockIdx.x * 16 + warp * 2;
    if (rowA >= rows_total) return;
    const int row  = rowA + (lane >> 4);
    const int base = (row >> LOG2_K) << LOG2_K;

    const int   idx = n_idxs[rowA * 16 + lane];
    const int   v   = nvalid[rowA * 16 + lane];
    const float vf  = (float)v;
    const float* rp = nrel + (size_t)rowA * 48 + lane * 3;
    float r0 = rp[0] * vf, r1 = rp[1] * vf, r2 = rp[2] * vf, cnt = vf;

    eidx[rowA * 16 + lane] = v ? (base + idx) : ZROW;

    #pragma unroll
    for (int m = 1; m < 16; m <<= 1) {
        r0  += __shfl_xor_sync(0xffffffffu, r0,  m);
        r1  += __shfl_xor_sync(0xffffffffu, r1,  m);
        r2  += __shfl_xor_sync(0xffffffffu, r2,  m);
        cnt += __shfl_xor_sync(0xffffffffu, cnt, m);
    }
    if ((lane & 15) == 0) {
        const float inv = (cnt > 0.0f) ? (1.0f / cnt) : 0.0f;
        meta[row] = make_float4(r0, r1, r2, inv);
    }
}

// ---------------------------------------------------------------------------
// Kernel 1: pf = feats @ Wf^T via HMMA m16n8k16 (fp16 in, fp32 acc).
// Block = 256 thr (8 warps), tile 128 rows x 64 outs; warp = 16 rows.
// ---------------------------------------------------------------------------
#define A_STRIDE 72   // halves per row (144B, conflict-free ldmatrix)
#define W_STRIDE 66

__global__ __launch_bounds__(256)
void proj_kernel(const float* __restrict__ feats,
                 const float* __restrict__ W,     // [64][67]
                 __half*      __restrict__ pf)
{
    __shared__ __half a_s[128 * A_STRIDE];
    __shared__ __half w_s[64 * W_STRIDE];

    const int tid = threadIdx.x;

    // stage W (feat part) as fp16, out-major
    for (int i = tid; i < 64 * 64; i += 256) {
        int o = i >> 6, k = i & 63;
        w_s[o * W_STRIDE + k] = __float2half(W[o * 67 + k]);
    }
    // stage feats tile 128x64 as fp16 (thread = half row)
    {
        const float4* fg = reinterpret_cast<const float4*>(feats)
                           + (size_t)blockIdx.x * (128 * 16);
        const int row = tid >> 1;
        const int hs  = tid & 1;
        #pragma unroll
        for (int i = 0; i < 8; i++) {
            float4 v = fg[row * 16 + hs * 8 + i];
            __half2* dst = reinterpret_cast<__half2*>(
                a_s + row * A_STRIDE + hs * 32 + i * 4);
            dst[0] = __floats2half2_rn(v.x, v.y);
            dst[1] = __floats2half2_rn(v.z, v.w);
        }
    }
    __syncthreads();

    const int warp = tid >> 5;
    const int lane = tid & 31;
    const int g    = lane >> 2;
    const int t4   = lane & 3;

    float d[8][4];
    #pragma unroll
    for (int nt = 0; nt < 8; nt++)
        d[nt][0] = d[nt][1] = d[nt][2] = d[nt][3] = 0.0f;

    // ldmatrix lane address: row = warp*16 + (lane&15), colh = (lane>>4)*8
    const uint32_t a_base = smem_u32(a_s)
        + ((warp * 16 + (lane & 15)) * A_STRIDE + (lane >> 4) * 8) * 2;
    const __half* wrow = w_s + g * W_STRIDE + t4 * 2;

    #pragma unroll
    for (int kt = 0; kt < 4; kt++) {
        uint32_t a0, a1, a2, a3;
        asm volatile(
            "ldmatrix.sync.aligned.m8n8.x4.shared.b16 {%0,%1,%2,%3}, [%4];"
            : "=r"(a0), "=r"(a1), "=r"(a2), "=r"(a3)
            : "r"(a_base + kt * 32));
        #pragma unroll
        for (int nt = 0; nt < 8; nt++) {
            const __half* wp = wrow + nt * 8 * W_STRIDE + kt * 16;
            const uint32_t b0 = *reinterpret_cast<const uint32_t*>(wp);
            const uint32_t b1 = *reinterpret_cast<const uint32_t*>(wp + 8);
            asm volatile(
                "mma.sync.aligned.m16n8k16.row.col.f32.f16.f16.f32 "
                "{%0,%1,%2,%3}, {%4,%5,%6,%7}, {%8,%9}, {%0,%1,%2,%3};"
                : "+f"(d[nt][0]), "+f"(d[nt][1]), "+f"(d[nt][2]), "+f"(d[nt][3])
                : "r"(a0), "r"(a1), "r"(a2), "r"(a3), "r"(b0), "r"(b1));
        }
    }

    // store fp16: d0,d1 -> row g, cols 2t4; d2,d3 -> row g+8
    const size_t row0 = (size_t)blockIdx.x * 128 + warp * 16 + g;
    #pragma unroll
    for (int nt = 0; nt < 8; nt++) {
        const int col = nt * 8 + t4 * 2;
        *reinterpret_cast<__half2*>(pf + row0 * 64 + col)
            = __floats2half2_rn(d[nt][0], d[nt][1]);
        *reinterpret_cast<__half2*>(pf + (row0 + 8) * 64 + col)
            = __floats2half2_rn(d[nt][2], d[nt][3]);
    }
}

// ---------------------------------------------------------------------------
// Kernel 2: gather-sum. 16 lanes/row, 2 rows/warp; 16 unconditional LDG.64
// from precomputed absolute indices; rel/inv from meta broadcast.
// ---------------------------------------------------------------------------
#define THREADS 256
#define CHUNKS_PER_BLOCK 2
#define ROWS_PER_CHUNK 16

__global__ __launch_bounds__(THREADS)
void gather_kernel(const __half* __restrict__ pf,
                   const int*    __restrict__ eidx,
                   const float4* __restrict__ meta,
                   const float*  __restrict__ W,     // [64][67]
                   const float*  __restrict__ bias,
                   float*        __restrict__ out,
                   int rows_total)
{
    __shared__ float wr_s[3 * 64];
    __shared__ float b_s[64];

    const int tid = threadIdx.x;
    for (int i = tid; i < 192; i += THREADS) {
        int jc = i >> 6, o = i & 63;
        wr_s[i] = W[o * 67 + 64 + jc];
    }
    if (tid < 64) b_s[tid] = bias[tid];
    __syncthreads();

    const int warp = tid >> 5;
    const int lane = tid & 31;
    const int g    = lane >> 4;
    const int t    = lane & 15;

    const float4* wr4 = reinterpret_cast<const float4*>(wr_s);
    const float4  b4  = reinterpret_cast<const float4*>(b_s)[t];
    const float4  w0  = wr4[0 * 16 + t];
    const float4  w1  = wr4[1 * 16 + t];
    const float4  w2  = wr4[2 * 16 + t];

    const uint2* pg = reinterpret_cast<const uint2*>(pf);

    for (int chunk = 0; chunk < CHUNKS_PER_BLOCK; chunk++) {
        const int rowA = (blockIdx.x * CHUNKS_PER_BLOCK + chunk) * ROWS_PER_CHUNK
                         + warp * 2;
        if (rowA >= rows_total) return;
        const int row = rowA + g;

        const int4* ep = reinterpret_cast<const int4*>(eidx + row * 16);
        const int4 ea = ep[0], eb = ep[1], ec = ep[2], ed = ep[3];
        const float4 mt = meta[row];

        const uint2 h0  = pg[(size_t)ea.x * 16 + t];
        const uint2 h1  = pg[(size_t)ea.y * 16 + t];
        const uint2 h2  = pg[(size_t)ea.z * 16 + t];
        const uint2 h3  = pg[(size_t)ea.w * 16 + t];
        const uint2 h4  = pg[(size_t)eb.x * 16 + t];
        const uint2 h5  = pg[(size_t)eb.y * 16 + t];
        const uint2 h6  = pg[(size_t)eb.z * 16 + t];
        const uint2 h7  = pg[(size_t)eb.w * 16 + t];
        const uint2 h8  = pg[(size_t)ec.x * 16 + t];
        const uint2 h9  = pg[(size_t)ec.y * 16 + t];
        const uint2 h10 = pg[(size_t)ec.z * 16 + t];
        const uint2 h11 = pg[(size_t)ec.w * 16 + t];
        const uint2 h12 = pg[(size_t)ed.x * 16 + t];
        const uint2 h13 = pg[(size_t)ed.y * 16 + t];
        const uint2 h14 = pg[(size_t)ed.z * 16 + t];
        const uint2 h15 = pg[(size_t)ed.w * 16 + t];

        float a0 = 0.f, a1 = 0.f, a2 = 0.f, a3 = 0.f;
        #define ACCUM(H) do {                                                  \
            const float2 f0 = __half22float2(*reinterpret_cast<const __half2*>(&(H).x)); \
            const float2 f1 = __half22float2(*reinterpret_cast<const __half2*>(&(H).y)); \
            a0 += f0.x; a1 += f0.y; a2 += f1.x; a3 += f1.y;                    \
        } while (0)
        ACCUM(h0);  ACCUM(h1);  ACCUM(h2);  ACCUM(h3);
        ACCUM(h4);  ACCUM(h5);  ACCUM(h6);  ACCUM(h7);
        ACCUM(h8);  ACCUM(h9);  ACCUM(h10); ACCUM(h11);
        ACCUM(h12); ACCUM(h13); ACCUM(h14); ACCUM(h15);
        #undef ACCUM

        a0 = fmaf(mt.x, w0.x, a0); a1 = fmaf(mt.x, w0.y, a1);
        a2 = fmaf(mt.x, w0.z, a2); a3 = fmaf(mt.x, w0.w, a3);
        a0 = fmaf(mt.y, w1.x, a0); a1 = fmaf(mt.y, w1.y, a1);
        a2 = fmaf(mt.y, w1.z, a2); a3 = fmaf(mt.y, w1.w, a3);
        a0 = fmaf(mt.z, w2.x, a0); a1 = fmaf(mt.z, w2.y, a1);
        a2 = fmaf(mt.z, w2.z, a2); a3 = fmaf(mt.z, w2.w, a3);

        float4 res;
        res.x = fmaxf(fmaf(a0, mt.w, b4.x), 0.0f);
        res.y = fmaxf(fmaf(a1, mt.w, b4.y), 0.0f);
        res.z = fmaxf(fmaf(a2, mt.w, b4.z), 0.0f);
        res.w = fmaxf(fmaf(a3, mt.w, b4.w), 0.0f);
        reinterpret_cast<float4*>(out)[(size_t)row * 16 + t] = res;
    }
}

extern "C" void kernel_launch(void* const* d_in, const int* in_sizes, int n_in,
                              void* d_out, int out_size)
{
    // metadata order: keys, points, feats, n_idxs, neighbor_rel,
    //                 neighbor_valid, W, b
    const float* feats  = (const float*)d_in[2];
    const int*   n_idxs = (const int*)  d_in[3];
    const float* nrel   = (const float*)d_in[4];
    const int*   nvalid = (const int*)  d_in[5];
    const float* W      = (const float*)d_in[6];
    const float* bias   = (const float*)d_in[7];
    float*       out    = (float*)d_out;

    const int rows_total = out_size / 64;   // 131072

    __half* pf   = nullptr;
    int*    eidx = nullptr;
    float4* meta = nullptr;
    cudaGetSymbolAddress((void**)&pf,   g_pf);
    cudaGetSymbolAddress((void**)&eidx, g_eidx);
    cudaGetSymbolAddress((void**)&meta, g_meta);

    meta_kernel<<<(rows_total + 15) / 16, 256>>>(n_idxs, nvalid, nrel,
                                                 eidx, meta, pf, rows_total);
    proj_kernel<<<rows_total / 128, 256>>>(feats, W, pf);

    const int rows_per_block = CHUNKS_PER_BLOCK * ROWS_PER_CHUNK;  // 32
    const int grid = (rows_total + rows_per_block - 1) / rows_per_block;
    gather_kernel<<<grid, THREADS>>>(pf, eidx, meta, W, bias, out, rows_total);
}